// round 1
// baseline (speedup 1.0000x reference)
#include <cuda_runtime.h>
#include <math.h>

#define Bn    16384
#define Dn    1024
#define Hn    512
#define En    16
#define KSEL  2
#define NSLOT (Bn * KSEL)   // 32768 assignments

#define EPSF  2.2204460492503131e-16f

// ---------------- device scratch (static allocation: allowed) ----------------
__device__ int   g_counts[En];
__device__ int   g_offsets[En];
__device__ int   g_cursor[En];
__device__ int   g_slot_row[NSLOT];    // slot -> source row
__device__ float g_slot_gate[NSLOT];   // slot -> gate
__device__ int   g_row_slot[NSLOT];    // (row,k) -> slot
__device__ int   g_expert_of[NSLOT];   // (row,k) -> expert
__device__ float g_gate_of[NSLOT];     // (row,k) -> gate
__device__ float g_ys[(size_t)NSLOT * Hn];   // gate * exp(y) per assignment (64 MB)

// ---------------- kernel 0: zero counts ----------------
__global__ void k_init() {
    int t = threadIdx.x;
    if (t < En) g_counts[t] = 0;
}

// ---------------- kernel 1: router (one warp per row) ----------------
__global__ void k_router(const float* __restrict__ x, const float* __restrict__ wr) {
    const int warp = threadIdx.x >> 5;
    const int lane = threadIdx.x & 31;
    const int row  = blockIdx.x * (blockDim.x >> 5) + warp;
    if (row >= Bn) return;

    float acc[En];
#pragma unroll
    for (int e = 0; e < En; e++) acc[e] = 0.f;

    const float* xr = x + (size_t)row * Dn;
    for (int d = lane; d < Dn; d += 32) {
        const float xv = xr[d];
        const float4* w4 = (const float4*)(wr + (size_t)d * En);
        float4 w0 = w4[0], w1 = w4[1], w2 = w4[2], w3 = w4[3];
        acc[0]  += xv * w0.x; acc[1]  += xv * w0.y; acc[2]  += xv * w0.z; acc[3]  += xv * w0.w;
        acc[4]  += xv * w1.x; acc[5]  += xv * w1.y; acc[6]  += xv * w1.z; acc[7]  += xv * w1.w;
        acc[8]  += xv * w2.x; acc[9]  += xv * w2.y; acc[10] += xv * w2.z; acc[11] += xv * w2.w;
        acc[12] += xv * w3.x; acc[13] += xv * w3.y; acc[14] += xv * w3.z; acc[15] += xv * w3.w;
    }
#pragma unroll
    for (int off = 16; off > 0; off >>= 1) {
#pragma unroll
        for (int e = 0; e < En; e++)
            acc[e] += __shfl_xor_sync(0xffffffffu, acc[e], off);
    }

    if (lane == 0) {
        // top-2 (first occurrence wins ties, matching lax.top_k)
        float v1 = -INFINITY; int i1 = 0;
#pragma unroll
        for (int e = 0; e < En; e++) { if (acc[e] > v1) { v1 = acc[e]; i1 = e; } }
        float v2 = -INFINITY; int i2 = 0;
#pragma unroll
        for (int e = 0; e < En; e++) { if (e != i1 && acc[e] > v2) { v2 = acc[e]; i2 = e; } }

        // softmax over {v1, v2}, v1 >= v2
        const float e2 = expf(v2 - v1);
        const float inv = 1.0f / (1.0f + e2);
        const float g1 = inv;
        const float g2 = e2 * inv;

        g_expert_of[row * 2 + 0] = i1;
        g_expert_of[row * 2 + 1] = i2;
        g_gate_of  [row * 2 + 0] = g1;
        g_gate_of  [row * 2 + 1] = g2;
        atomicAdd(&g_counts[i1], 1);
        atomicAdd(&g_counts[i2], 1);
    }
}

// ---------------- kernel 2: exclusive scan over 16 experts ----------------
__global__ void k_scan() {
    if (threadIdx.x == 0) {
        int s = 0;
        for (int e = 0; e < En; e++) {
            g_offsets[e] = s;
            g_cursor[e]  = s;
            s += g_counts[e];
        }
    }
}

// ---------------- kernel 3: scatter rows into expert buckets ----------------
__global__ void k_scatter() {
    const int row = blockIdx.x * blockDim.x + threadIdx.x;
    if (row >= Bn) return;
#pragma unroll
    for (int k = 0; k < KSEL; k++) {
        const int e    = g_expert_of[row * 2 + k];
        const int slot = atomicAdd(&g_cursor[e], 1);
        g_slot_row [slot] = row;
        g_slot_gate[slot] = g_gate_of[row * 2 + k];
        g_row_slot[row * 2 + k] = slot;
    }
}

// ---------------- kernel 4: grouped expert GEMM (fp32 SIMT) ----------------
// Tile: BM=64, BN=64, BK=16. 256 threads, 4x4 micro-tile per thread.
// blockIdx.x enumerates row tiles across all experts; blockIdx.y = column tile.
#define MAX_ROW_TILES 544

__global__ __launch_bounds__(256) void k_gemm(const float* __restrict__ x,
                                              const float* __restrict__ we) {
    __shared__ float As[16][68];      // [k][row], stride keeps 16B alignment
    __shared__ float Bs[16][64];      // [k][h]
    __shared__ int   srow[64];
    __shared__ float sgate[64];
    __shared__ int   s_e, s_start, s_m;

    const int tid = threadIdx.x;

    if (tid == 0) {
        int t = blockIdx.x, acc = 0, fe = -1, ti = 0;
        for (int e = 0; e < En; e++) {
            const int nt = (g_counts[e] + 63) >> 6;
            if (t < acc + nt) { fe = e; ti = t - acc; break; }
            acc += nt;
        }
        s_e = fe;
        if (fe >= 0) {
            s_start = g_offsets[fe] + ti * 64;
            const int rem = g_counts[fe] - ti * 64;
            s_m = rem < 64 ? rem : 64;
        }
    }
    __syncthreads();
    const int e = s_e;
    if (e < 0) return;
    const int start = s_start;
    const int m     = s_m;

    if (tid < 64) {
        if (tid < m) {
            srow [tid] = g_slot_row [start + tid];
            sgate[tid] = g_slot_gate[start + tid];
        } else {
            srow [tid] = -1;
            sgate[tid] = 0.f;
        }
    }
    __syncthreads();

    const int hbase = blockIdx.y * 64;
    const int tx = tid & 15;
    const int ty = tid >> 4;

    float acc[4][4];
#pragma unroll
    for (int i = 0; i < 4; i++)
#pragma unroll
        for (int j = 0; j < 4; j++) acc[i][j] = 0.f;

    const float* wbase = we + (size_t)e * Dn * Hn;

    // load-index decomposition
    const int ar = tid >> 2;           // 0..63  (tile row for A load)
    const int ak = (tid & 3) * 4;      // 0,4,8,12 (k sub-segment)
    const int br = tid >> 4;           // 0..15  (k row for B load)
    const int bh = (tid & 15) * 4;     // h sub-segment

    const int arow = srow[ar];
    const float* aptr = (arow >= 0) ? (x + (size_t)arow * Dn + ak) : nullptr;

    for (int kk = 0; kk < Dn; kk += 16) {
        float4 av = make_float4(0.f, 0.f, 0.f, 0.f);
        if (aptr) av = *(const float4*)(aptr + kk);
        As[ak + 0][ar] = av.x;
        As[ak + 1][ar] = av.y;
        As[ak + 2][ar] = av.z;
        As[ak + 3][ar] = av.w;

        const float4 bv = *(const float4*)(wbase + (size_t)(kk + br) * Hn + hbase + bh);
        *(float4*)&Bs[br][bh] = bv;
        __syncthreads();

#pragma unroll
        for (int k = 0; k < 16; k++) {
            const float4 a4 = *(const float4*)&As[k][ty * 4];
            const float4 b4 = *(const float4*)&Bs[k][tx * 4];
            acc[0][0] += a4.x * b4.x; acc[0][1] += a4.x * b4.y; acc[0][2] += a4.x * b4.z; acc[0][3] += a4.x * b4.w;
            acc[1][0] += a4.y * b4.x; acc[1][1] += a4.y * b4.y; acc[1][2] += a4.y * b4.z; acc[1][3] += a4.y * b4.w;
            acc[2][0] += a4.z * b4.x; acc[2][1] += a4.z * b4.y; acc[2][2] += a4.z * b4.z; acc[2][3] += a4.z * b4.w;
            acc[3][0] += a4.w * b4.x; acc[3][1] += a4.w * b4.y; acc[3][2] += a4.w * b4.z; acc[3][3] += a4.w * b4.w;
        }
        __syncthreads();
    }

    // epilogue: ys[slot][h] = gate * exp(y)
#pragma unroll
    for (int i = 0; i < 4; i++) {
        const int r = ty * 4 + i;
        if (r < m) {
            const int   slot = start + r;
            const float g    = sgate[r];
            float4 o;
            o.x = g * expf(acc[i][0]);
            o.y = g * expf(acc[i][1]);
            o.z = g * expf(acc[i][2]);
            o.w = g * expf(acc[i][3]);
            *(float4*)&g_ys[(size_t)slot * Hn + hbase + tx * 4] = o;
        }
    }
}

// ---------------- kernel 5: combine ----------------
__global__ void k_combine(float* __restrict__ out) {
    const size_t i = (size_t)blockIdx.x * blockDim.x + threadIdx.x;   // over B*H/4
    if (i >= (size_t)Bn * Hn / 4) return;
    const int row = (int)(i / (Hn / 4));
    const int seg = (int)(i % (Hn / 4));
    const int s1 = g_row_slot[row * 2 + 0];
    const int s2 = g_row_slot[row * 2 + 1];
    const float4 a = *(const float4*)&g_ys[(size_t)s1 * Hn + seg * 4];
    const float4 b = *(const float4*)&g_ys[(size_t)s2 * Hn + seg * 4];
    float4 o;
    float c;
    c = a.x + b.x; if (c == 0.f) c = EPSF; o.x = logf(c);
    c = a.y + b.y; if (c == 0.f) c = EPSF; o.y = logf(c);
    c = a.z + b.z; if (c == 0.f) c = EPSF; o.z = logf(c);
    c = a.w + b.w; if (c == 0.f) c = EPSF; o.w = logf(c);
    ((float4*)out)[i] = o;
}

// ---------------- launch ----------------
extern "C" void kernel_launch(void* const* d_in, const int* in_sizes, int n_in,
                              void* d_out, int out_size) {
    const float* x  = (const float*)d_in[0];   // [B, D]
    const float* wr = (const float*)d_in[1];   // [D, E]
    const float* we = (const float*)d_in[2];   // [E, D, H]
    float* out = (float*)d_out;                // [B, H]

    k_init<<<1, 32>>>();
    k_router<<<Bn / 8, 256>>>(x, wr);
    k_scan<<<1, 32>>>();
    k_scatter<<<Bn / 256, 256>>>();
    dim3 ggrid(MAX_ROW_TILES, Hn / 64);
    k_gemm<<<ggrid, 256>>>(x, we);
    k_combine<<<(Bn * Hn / 4 + 255) / 256, 256>>>(out);
}

// round 3
// speedup vs baseline: 2.0938x; 2.0938x over previous
#include <cuda_runtime.h>
#include <cuda_bf16.h>
#include <math.h>
#include <stdint.h>

#define Bn    16384
#define Dn    1024
#define Hn    512
#define En    16
#define KSEL  2
#define NSLOT (Bn * KSEL)

#define EPSF  2.2204460492503131e-16f

// ---------------- device scratch ----------------
__device__ int   g_counts[En];
__device__ int   g_offsets[En];
__device__ int   g_cursor[En];
__device__ int   g_slot_row[NSLOT];
__device__ float g_slot_gate[NSLOT];
__device__ int   g_row_slot[NSLOT];
__device__ int   g_expert_of[NSLOT];
__device__ float g_gate_of[NSLOT];
__device__ float g_ys[(size_t)NSLOT * Hn];                    // 64 MB
__device__ __nv_bfloat16 g_xh[(size_t)Bn * Dn];               // 32 MB
__device__ __nv_bfloat16 g_xl[(size_t)Bn * Dn];               // 32 MB
__device__ __nv_bfloat16 g_wth[(size_t)En * Hn * Dn];         // 16 MB  [E][H][D]
__device__ __nv_bfloat16 g_wtl[(size_t)En * Hn * Dn];         // 16 MB

// ---------------- helpers ----------------
__device__ __forceinline__ uint32_t smem_u32(const void* p) {
    uint32_t a;
    asm("{ .reg .u64 t; cvta.to.shared.u64 t, %1; cvt.u32.u64 %0, t; }" : "=r"(a) : "l"(p));
    return a;
}
#define SW128(o) ((o) ^ (((o) >> 3) & 0x70))

__device__ __forceinline__ void cp16(uint32_t dst, const void* src) {
    asm volatile("cp.async.cg.shared.global [%0], [%1], 16;" :: "r"(dst), "l"(src) : "memory");
}
#define CP_COMMIT() asm volatile("cp.async.commit_group;" ::: "memory")
#define CP_WAIT2()  asm volatile("cp.async.wait_group 2;" ::: "memory")

__device__ __forceinline__ void ldsm4(uint32_t* r, uint32_t tile_base, int row0,
                                      int kbyte, int lane) {
    const uint32_t off = (uint32_t)((row0 + (lane & 15)) * 128 + kbyte + ((lane >> 4) * 16));
    const uint32_t addr = tile_base + SW128(off);
    asm volatile("ldmatrix.sync.aligned.m8n8.x4.shared.b16 {%0,%1,%2,%3}, [%4];"
                 : "=r"(r[0]), "=r"(r[1]), "=r"(r[2]), "=r"(r[3]) : "r"(addr));
}

__device__ __forceinline__ void mma16816(float* c, const uint32_t* a,
                                         uint32_t b0, uint32_t b1) {
    asm volatile(
        "mma.sync.aligned.m16n8k16.row.col.f32.bf16.bf16.f32 "
        "{%0,%1,%2,%3}, {%4,%5,%6,%7}, {%8,%9}, {%0,%1,%2,%3};"
        : "+f"(c[0]), "+f"(c[1]), "+f"(c[2]), "+f"(c[3])
        : "r"(a[0]), "r"(a[1]), "r"(a[2]), "r"(a[3]), "r"(b0), "r"(b1));
}

// ---------------- kernel 0: zero counts ----------------
__global__ void k_init() {
    int t = threadIdx.x;
    if (t < En) g_counts[t] = 0;
}

// ---------------- kernel 1: router ----------------
__global__ void k_router(const float* __restrict__ x, const float* __restrict__ wr) {
    const int warp = threadIdx.x >> 5;
    const int lane = threadIdx.x & 31;
    const int row  = blockIdx.x * (blockDim.x >> 5) + warp;
    if (row >= Bn) return;

    float acc[En];
#pragma unroll
    for (int e = 0; e < En; e++) acc[e] = 0.f;

    const float* xr = x + (size_t)row * Dn;
    for (int d = lane; d < Dn; d += 32) {
        const float xv = xr[d];
        const float4* w4 = (const float4*)(wr + (size_t)d * En);
        float4 w0 = w4[0], w1 = w4[1], w2 = w4[2], w3 = w4[3];
        acc[0]  += xv * w0.x; acc[1]  += xv * w0.y; acc[2]  += xv * w0.z; acc[3]  += xv * w0.w;
        acc[4]  += xv * w1.x; acc[5]  += xv * w1.y; acc[6]  += xv * w1.z; acc[7]  += xv * w1.w;
        acc[8]  += xv * w2.x; acc[9]  += xv * w2.y; acc[10] += xv * w2.z; acc[11] += xv * w2.w;
        acc[12] += xv * w3.x; acc[13] += xv * w3.y; acc[14] += xv * w3.z; acc[15] += xv * w3.w;
    }
#pragma unroll
    for (int off = 16; off > 0; off >>= 1) {
#pragma unroll
        for (int e = 0; e < En; e++)
            acc[e] += __shfl_xor_sync(0xffffffffu, acc[e], off);
    }

    if (lane == 0) {
        float v1 = -INFINITY; int i1 = 0;
#pragma unroll
        for (int e = 0; e < En; e++) { if (acc[e] > v1) { v1 = acc[e]; i1 = e; } }
        float v2 = -INFINITY; int i2 = 0;
#pragma unroll
        for (int e = 0; e < En; e++) { if (e != i1 && acc[e] > v2) { v2 = acc[e]; i2 = e; } }
        const float e2 = expf(v2 - v1);
        const float inv = 1.0f / (1.0f + e2);
        g_expert_of[row * 2 + 0] = i1;
        g_expert_of[row * 2 + 1] = i2;
        g_gate_of  [row * 2 + 0] = inv;
        g_gate_of  [row * 2 + 1] = e2 * inv;
        atomicAdd(&g_counts[i1], 1);
        atomicAdd(&g_counts[i2], 1);
    }
}

// ---------------- kernel 2: scan ----------------
__global__ void k_scan() {
    if (threadIdx.x == 0) {
        int s = 0;
        for (int e = 0; e < En; e++) {
            g_offsets[e] = s;
            g_cursor[e]  = s;
            s += g_counts[e];
        }
    }
}

// ---------------- kernel 3: scatter ----------------
__global__ void k_scatter() {
    const int row = blockIdx.x * blockDim.x + threadIdx.x;
    if (row >= Bn) return;
#pragma unroll
    for (int k = 0; k < KSEL; k++) {
        const int e    = g_expert_of[row * 2 + k];
        const int slot = atomicAdd(&g_cursor[e], 1);
        g_slot_row [slot] = row;
        g_slot_gate[slot] = g_gate_of[row * 2 + k];
        g_row_slot[row * 2 + k] = slot;
    }
}

// ---------------- kernel 3b: split x into bf16 hi/lo ----------------
__global__ void k_convert_x(const float* __restrict__ x) {
    const size_t i = ((size_t)blockIdx.x * blockDim.x + threadIdx.x) * 8;
    float4 a = *(const float4*)(x + i);
    float4 b = *(const float4*)(x + i + 4);
    float v[8] = {a.x, a.y, a.z, a.w, b.x, b.y, b.z, b.w};
    __nv_bfloat16 h[8], l[8];
#pragma unroll
    for (int t = 0; t < 8; t++) {
        h[t] = __float2bfloat16(v[t]);
        l[t] = __float2bfloat16(v[t] - __bfloat162float(h[t]));
    }
    *(uint4*)&g_xh[i] = *(uint4*)h;
    *(uint4*)&g_xl[i] = *(uint4*)l;
}

// ---------------- kernel 3c: transpose + split weights ----------------
// w [E][D][H] fp32 -> g_wth/g_wtl [E][H][D] bf16
__global__ void k_convert_w(const float* __restrict__ w) {
    __shared__ float t[32][33];
    const int e  = blockIdx.z;
    const int d0 = blockIdx.x * 32;
    const int h0 = blockIdx.y * 32;
    const int tx = threadIdx.x, ty = threadIdx.y;

    for (int j = ty; j < 32; j += 8)
        t[j][tx] = w[((size_t)e * Dn + d0 + j) * Hn + h0 + tx];
    __syncthreads();
    for (int j = ty; j < 32; j += 8) {
        const float v = t[tx][j];
        const __nv_bfloat16 hi = __float2bfloat16(v);
        const __nv_bfloat16 lo = __float2bfloat16(v - __bfloat162float(hi));
        const size_t o = ((size_t)e * Hn + h0 + j) * Dn + d0 + tx;
        g_wth[o] = hi;
        g_wtl[o] = lo;
    }
}

// ---------------- kernel 4: grouped warp-MMA GEMM (bf16 hi/lo, 3 terms) --------
// BM=128, BN=128, BK=64. 8 warps (2M x 4N), warp tile 64x32.
// 3-stage cp.async pipeline, SW128-swizzled K-major smem tiles.
#define BM 128
#define BN 128
#define BK 64
#define NCHUNK (Dn / BK)          // 16
#define MAX_ROW_TILES 272

#define STAGE_BYTES 65536          // Ah 16K | Al 16K | Bh 16K | Bl 16K
#define AH_OFF 0
#define AL_OFF 16384
#define BH_OFF 32768
#define BL_OFF 49152
#define CTRL_OFF (3 * STAGE_BYTES)                 // 196608
#define SMEM_BYTES (CTRL_OFF + 2048 + 1024)

__global__ __launch_bounds__(256, 1) void k_gemm() {
    extern __shared__ char smem_raw[];
    const uint32_t sb_raw = smem_u32(smem_raw);
    const uint32_t sb = (sb_raw + 1023u) & ~1023u;
    char* smem = smem_raw + (sb - sb_raw);

    const int tid  = threadIdx.x;
    const int wid  = tid >> 5;
    const int lane = tid & 31;

    int*   srow  = (int*)(smem + CTRL_OFF);
    float* sgate = (float*)(smem + CTRL_OFF + 512);
    int*   meta  = (int*)(smem + CTRL_OFF + 1024);

    if (tid == 0) {
        int t = blockIdx.x, acc = 0, fe = -1, ti = 0;
        for (int e = 0; e < En; e++) {
            const int nt = (g_counts[e] + BM - 1) / BM;
            if (t < acc + nt) { fe = e; ti = t - acc; break; }
            acc += nt;
        }
        meta[0] = fe;
        if (fe >= 0) {
            meta[1] = g_offsets[fe] + ti * BM;
            const int rem = g_counts[fe] - ti * BM;
            meta[2] = rem < BM ? rem : BM;
        }
    }
    __syncthreads();
    const int e = meta[0];
    if (e < 0) return;
    const int start = meta[1];
    const int m     = meta[2];

    if (tid < BM) {
        const int slot = (tid < m) ? start + tid : start;
        srow[tid]  = g_slot_row[slot];
        sgate[tid] = (tid < m) ? g_slot_gate[start + tid] : 0.f;
    }
    __syncthreads();

    const int hbase = blockIdx.y * BN;
    const __nv_bfloat16* wth = g_wth + ((size_t)e * Hn + hbase) * Dn;
    const __nv_bfloat16* wtl = g_wtl + ((size_t)e * Hn + hbase) * Dn;

    // per-thread load slots: 128 rows x 8 chunks of 16B per 16KB tile
    const __nv_bfloat16* axh[4];
    const __nv_bfloat16* axl[4];
    const __nv_bfloat16* bwh[4];
    const __nv_bfloat16* bwl[4];
    uint32_t aoff[4];
#pragma unroll
    for (int j = 0; j < 4; j++) {
        const int u = tid + j * 256;
        const int r = u >> 3, c = u & 7;
        axh[j] = g_xh + (size_t)srow[r] * Dn + c * 8;
        axl[j] = g_xl + (size_t)srow[r] * Dn + c * 8;
        bwh[j] = wth + (size_t)r * Dn + c * 8;
        bwl[j] = wtl + (size_t)r * Dn + c * 8;
        aoff[j] = SW128((uint32_t)(r * 128 + c * 16));
    }

#define LOAD_CHUNK(cc) do {                                                    \
    const int s_  = (cc) % 3;                                                  \
    const int kk_ = (cc) * BK;                                                 \
    const uint32_t base_ = sb + s_ * STAGE_BYTES;                              \
    _Pragma("unroll")                                                          \
    for (int j = 0; j < 4; j++) {                                              \
        cp16(base_ + AH_OFF + aoff[j], axh[j] + kk_);                          \
        cp16(base_ + AL_OFF + aoff[j], axl[j] + kk_);                          \
        cp16(base_ + BH_OFF + aoff[j], bwh[j] + kk_);                          \
        cp16(base_ + BL_OFF + aoff[j], bwl[j] + kk_);                          \
    }                                                                          \
} while (0)

    const int wm = (wid >> 2) * 64;    // 0 / 64
    const int wn = (wid & 3) * 32;     // 0..96

    float acc[4][4][4];
#pragma unroll
    for (int i = 0; i < 4; i++)
#pragma unroll
        for (int j = 0; j < 4; j++)
#pragma unroll
            for (int q = 0; q < 4; q++) acc[i][j][q] = 0.f;

    LOAD_CHUNK(0); CP_COMMIT();
    LOAD_CHUNK(1); CP_COMMIT();

    for (int ch = 0; ch < NCHUNK; ch++) {
        if (ch + 2 < NCHUNK) LOAD_CHUNK(ch + 2);
        CP_COMMIT();
        CP_WAIT2();
        __syncthreads();

        const uint32_t base = sb + (ch % 3) * STAGE_BYTES;
#pragma unroll
        for (int ks = 0; ks < 4; ks++) {
            const int kbyte = ks * 32;
            uint32_t ah[16], al[16], bh[8], bl[8];
#pragma unroll
            for (int i = 0; i < 4; i++) {
                ldsm4(ah + i * 4, base + AH_OFF, wm + i * 16, kbyte, lane);
                ldsm4(al + i * 4, base + AL_OFF, wm + i * 16, kbyte, lane);
            }
            ldsm4(bh,     base + BH_OFF, wn,      kbyte, lane);
            ldsm4(bh + 4, base + BH_OFF, wn + 16, kbyte, lane);
            ldsm4(bl,     base + BL_OFF, wn,      kbyte, lane);
            ldsm4(bl + 4, base + BL_OFF, wn + 16, kbyte, lane);

            // n8 tile j -> b regs: j0:{r0,r2} j1:{r1,r3} j2:{r4,r6} j3:{r5,r7}
            const int bi0[4] = {0, 1, 4, 5};
            const int bi1[4] = {2, 3, 6, 7};
#pragma unroll
            for (int i = 0; i < 4; i++) {
#pragma unroll
                for (int j = 0; j < 4; j++) {
                    mma16816(acc[i][j], ah + i * 4, bh[bi0[j]], bh[bi1[j]]);
                    mma16816(acc[i][j], ah + i * 4, bl[bi0[j]], bl[bi1[j]]);
                    mma16816(acc[i][j], al + i * 4, bh[bi0[j]], bh[bi1[j]]);
                }
            }
        }
        __syncthreads();
    }

    // epilogue: ys[slot][h] = gate * exp(acc)
#pragma unroll
    for (int i = 0; i < 4; i++) {
        const int r0 = wm + i * 16 + (lane >> 2);
        const int r1 = r0 + 8;
        const float g0 = sgate[r0];
        const float g1 = sgate[r1];
        float* d0 = g_ys + (size_t)(start + r0) * Hn + hbase + wn + (lane & 3) * 2;
        float* d1 = g_ys + (size_t)(start + r1) * Hn + hbase + wn + (lane & 3) * 2;
#pragma unroll
        for (int j = 0; j < 4; j++) {
            if (r0 < m) {
                float2 o;
                o.x = g0 * expf(acc[i][j][0]);
                o.y = g0 * expf(acc[i][j][1]);
                *(float2*)(d0 + j * 8) = o;
            }
            if (r1 < m) {
                float2 o;
                o.x = g1 * expf(acc[i][j][2]);
                o.y = g1 * expf(acc[i][j][3]);
                *(float2*)(d1 + j * 8) = o;
            }
        }
    }
}

// ---------------- kernel 5: combine ----------------
__global__ void k_combine(float* __restrict__ out) {
    const size_t i = (size_t)blockIdx.x * blockDim.x + threadIdx.x;
    if (i >= (size_t)Bn * Hn / 4) return;
    const int row = (int)(i / (Hn / 4));
    const int seg = (int)(i % (Hn / 4));
    const int s1 = g_row_slot[row * 2 + 0];
    const int s2 = g_row_slot[row * 2 + 1];
    const float4 a = *(const float4*)&g_ys[(size_t)s1 * Hn + seg * 4];
    const float4 b = *(const float4*)&g_ys[(size_t)s2 * Hn + seg * 4];
    float4 o;
    float c;
    c = a.x + b.x; if (c == 0.f) c = EPSF; o.x = logf(c);
    c = a.y + b.y; if (c == 0.f) c = EPSF; o.y = logf(c);
    c = a.z + b.z; if (c == 0.f) c = EPSF; o.z = logf(c);
    c = a.w + b.w; if (c == 0.f) c = EPSF; o.w = logf(c);
    ((float4*)out)[i] = o;
}

// ---------------- launch ----------------
extern "C" void kernel_launch(void* const* d_in, const int* in_sizes, int n_in,
                              void* d_out, int out_size) {
    const float* x  = (const float*)d_in[0];
    const float* wr = (const float*)d_in[1];
    const float* we = (const float*)d_in[2];
    float* out = (float*)d_out;

    cudaFuncSetAttribute(k_gemm, cudaFuncAttributeMaxDynamicSharedMemorySize, SMEM_BYTES);

    k_init<<<1, 32>>>();
    k_router<<<Bn / 8, 256>>>(x, wr);
    k_scan<<<1, 32>>>();
    k_scatter<<<Bn / 256, 256>>>();
    k_convert_x<<<(Bn * Dn) / (256 * 8), 256>>>(x);
    dim3 wgrid(Dn / 32, Hn / 32, En);
    k_convert_w<<<wgrid, dim3(32, 8)>>>(we);
    dim3 ggrid(MAX_ROW_TILES, Hn / BN);
    k_gemm<<<ggrid, 256, SMEM_BYTES>>>();
    k_combine<<<(Bn * Hn / 4 + 255) / 256, 256>>>(out);
}